// round 1
// baseline (speedup 1.0000x reference)
#include <cuda_runtime.h>
#include <math.h>

// ---------------- problem constants ----------------
#define S_LEN 2048
#define QKV_W 3072
#define DIM_  2048
#define DH_   64
#define KVH_  8
#define HEADS_ 32
#define CDIM_ 1024
#define NC_   128        // number of 16-token compression blocks
#define NEGV  (-1e30f)
#define SCALE_ 0.125f    // 64^-0.5

// ---------------- scratch (device globals; no allocations) ----------------
__device__ float g_qkv [S_LEN * QKV_W];            // (2048, 3072)
__device__ float g_kb  [KVH_ * NC_ * CDIM_];       // (8*128, 1024)
__device__ float g_vb  [KVH_ * NC_ * CDIM_];
__device__ float g_h1  [KVH_ * NC_ * CDIM_];       // relu intermediate (reused k then v)
__device__ float g_body[KVH_ * NC_ * DH_];         // (1024, 64) compressed body (reused)
__device__ float g_ck  [KVH_ * 129 * DH_];         // mem token + 128 blocks
__device__ float g_cv  [KVH_ * 129 * DH_];
__device__ float g_csim[HEADS_ * S_LEN * 129];     // [hg][n][129], masked
__device__ float g_cout[HEADS_ * S_LEN * DH_];     // [hg][n][64]
__device__ float g_fout[HEADS_ * S_LEN * DH_];
__device__ float g_sout[HEADS_ * S_LEN * DH_];
__device__ float g_rq  [HEADS_ * S_LEN * DH_];     // roped q  [hg][n][64]
__device__ float g_rk  [KVH_  * S_LEN * DH_];      // roped k  [h][n][64]
__device__ float g_rcs [S_LEN * 32 * 2];           // rope cos/sin table [n][pair][2]
__device__ int           g_selidx [KVH_ * S_LEN * 8];
__device__ unsigned char g_selmask[KVH_ * S_LEN * 8];
__device__ float g_gate[S_LEN * 96];
__device__ float g_pre [S_LEN * DIM_];

// ---------------- generic fp32 SGEMM: C = act(A@B + bias) ----------------
// A: MxK row-major, B: KxN row-major. ACT: 0 none, 1 relu, 2 sigmoid.
template <int ACT>
__global__ void sgemm_kernel(const float* __restrict__ A, const float* __restrict__ B,
                             const float* __restrict__ bias, float* __restrict__ C,
                             int M, int N, int K)
{
    __shared__ float As[8][128];
    __shared__ float Bs[8][128];
    const int tid = threadIdx.x;
    const int rowBase = blockIdx.y * 128;
    const int colBase = blockIdx.x * 128;
    const int ty = tid >> 4;   // 0..15
    const int tx = tid & 15;   // 0..15
    float acc[8][8];
#pragma unroll
    for (int i = 0; i < 8; ++i)
#pragma unroll
        for (int j = 0; j < 8; ++j) acc[i][j] = 0.f;

    for (int k0 = 0; k0 < K; k0 += 8) {
#pragma unroll
        for (int l = 0; l < 4; ++l) {
            int idx = tid + l * 256;
            int am = idx >> 3, ak = idx & 7;
            int arow = rowBase + am;
            As[ak][am] = (arow < M) ? A[(size_t)arow * K + k0 + ak] : 0.f;
            int bk = idx >> 7, bn = idx & 127;
            int bcol = colBase + bn;
            Bs[bk][bn] = (bcol < N) ? B[(size_t)(k0 + bk) * N + bcol] : 0.f;
        }
        __syncthreads();
#pragma unroll
        for (int kk = 0; kk < 8; ++kk) {
            float a[8], b[8];
#pragma unroll
            for (int i = 0; i < 8; ++i) a[i] = As[kk][ty * 8 + i];
#pragma unroll
            for (int j = 0; j < 8; ++j) b[j] = Bs[kk][tx * 8 + j];
#pragma unroll
            for (int i = 0; i < 8; ++i)
#pragma unroll
                for (int j = 0; j < 8; ++j)
                    acc[i][j] = fmaf(a[i], b[j], acc[i][j]);
        }
        __syncthreads();
    }
#pragma unroll
    for (int i = 0; i < 8; ++i) {
        int row = rowBase + ty * 8 + i;
        if (row >= M) continue;
#pragma unroll
        for (int j = 0; j < 8; ++j) {
            int col = colBase + tx * 8 + j;
            if (col >= N) continue;
            float v = acc[i][j];
            if (bias) v += bias[col];
            if (ACT == 1) v = fmaxf(v, 0.f);
            if (ACT == 2) v = 1.f / (1.f + expf(-v));
            C[(size_t)row * N + col] = v;
        }
    }
}

// ---------------- kb/vb construction ----------------
__global__ void build_kb_vb(const float* __restrict__ k_pos, const float* __restrict__ v_pos)
{
    int idx = blockIdx.x * blockDim.x + threadIdx.x;   // over 8*128*1024 = 2^20
    if (idx >= KVH_ * NC_ * CDIM_) return;
    int d = idx & 63;
    int i = (idx >> 6) & 15;
    int c = (idx >> 10) & 127;
    int h = idx >> 17;
    int t = c * 16 + i;
    float kv = g_qkv[(size_t)t * QKV_W + DIM_ + h * DH_ + d];
    float vv = g_qkv[(size_t)t * QKV_W + DIM_ + 512 + h * DH_ + d];
    g_kb[idx] = kv + k_pos[(h * 16 + i) * 64 + d];
    g_vb[idx] = vv + v_pos[(h * 16 + i) * 64 + d];
}

// ---------------- assemble ck/cv: prepend mem token ----------------
__global__ void assemble_c(const float* __restrict__ mem, float* __restrict__ dst)
{
    int idx = blockIdx.x * blockDim.x + threadIdx.x;   // 8*129*64
    if (idx >= KVH_ * 129 * DH_) return;
    int d = idx % 64;
    int j = (idx / 64) % 129;
    int h = idx / (64 * 129);
    dst[idx] = (j == 0) ? mem[h * 64 + d] : g_body[((h * NC_) + (j - 1)) * 64 + d];
}

// ---------------- compression similarities (masked, scaled) ----------------
__global__ void csim_kernel()
{
    int w = (blockIdx.x * blockDim.x + threadIdx.x) >> 5;
    int lane = threadIdx.x & 31;
    if (w >= HEADS_ * S_LEN) return;
    int hg = w >> 11, n = w & (S_LEN - 1);
    int h = hg >> 2;
    const float* q = g_qkv + (size_t)n * QKV_W + hg * DH_;
    float* out = g_csim + (size_t)w * 129;
    for (int j = lane; j < 129; j += 32) {
        bool valid = (j == 0) || (n >= 16 * j);
        float s = NEGV;
        if (valid) {
            const float* ckr = g_ck + ((h * 129) + j) * 64;
            float acc = 0.f;
#pragma unroll
            for (int d = 0; d < 64; ++d) acc = fmaf(q[d], ckr[d], acc);
            s = acc * SCALE_;
        }
        out[j] = s;
    }
}

// ---------------- compression attention output ----------------
__global__ void cout_kernel()
{
    __shared__ float sp[8][129];
    int w = (blockIdx.x * blockDim.x + threadIdx.x) >> 5;
    int lane = threadIdx.x & 31, wl = (threadIdx.x >> 5) & 7;
    if (w >= HEADS_ * S_LEN) return;
    int hg = w >> 11;
    int h = hg >> 2;
    const float* row = g_csim + (size_t)w * 129;
    float m = -1e38f;
    for (int j = lane; j < 129; j += 32) m = fmaxf(m, row[j]);
#pragma unroll
    for (int o = 16; o; o >>= 1) m = fmaxf(m, __shfl_xor_sync(0xffffffffu, m, o));
    float sum = 0.f;
    for (int j = lane; j < 129; j += 32) { float e = expf(row[j] - m); sp[wl][j] = e; sum += e; }
#pragma unroll
    for (int o = 16; o; o >>= 1) sum += __shfl_xor_sync(0xffffffffu, sum, o);
    __syncwarp();
    float inv = 1.f / sum;
    float a0 = 0.f, a1 = 0.f;
    const float* cvh = g_cv + h * 129 * 64;
    for (int j = 0; j < 129; ++j) {
        float p = sp[wl][j];
        a0 = fmaf(p, cvh[j * 64 + lane], a0);
        a1 = fmaf(p, cvh[j * 64 + lane + 32], a1);
    }
    g_cout[(size_t)w * 64 + lane]      = a0 * inv;
    g_cout[(size_t)w * 64 + lane + 32] = a1 * inv;
}

// ---------------- importance + top-8 selection ----------------
__global__ void topk_kernel()
{
    int w = (blockIdx.x * blockDim.x + threadIdx.x) >> 5;
    int lane = threadIdx.x & 31;
    if (w >= KVH_ * S_LEN) return;
    int h = w >> 11, n = w & (S_LEN - 1);
    float vals[4];
    int js[4];
#pragma unroll
    for (int r = 0; r < 4; ++r) {
        int jj = lane + r * 32;            // block index 0..127 (csim j = jj+1)
        float s = 0.f;
        for (int g = 0; g < 4; ++g)
            s += g_csim[(((size_t)(h * 4 + g) * S_LEN + n) * 129) + jj + 1];
        vals[r] = s * 0.25f;
        js[r] = jj;
    }
    // softmax denominator including dummy -1000
    float m = -1000.f;
#pragma unroll
    for (int r = 0; r < 4; ++r) m = fmaxf(m, vals[r]);
#pragma unroll
    for (int o = 16; o; o >>= 1) m = fmaxf(m, __shfl_xor_sync(0xffffffffu, m, o));
    float sum = 0.f;
#pragma unroll
    for (int r = 0; r < 4; ++r) sum += expf(vals[r] - m);
#pragma unroll
    for (int o = 16; o; o >>= 1) sum += __shfl_xor_sync(0xffffffffu, sum, o);
    sum += expf(-1000.f - m);
    // iterative top-8, lowest-index tie break (matches jax.lax.top_k)
    for (int t = 0; t < 8; ++t) {
        float bv = vals[0]; int bj = js[0];
#pragma unroll
        for (int r = 1; r < 4; ++r)
            if (vals[r] > bv || (vals[r] == bv && js[r] < bj)) { bv = vals[r]; bj = js[r]; }
        float v = bv; int j = bj;
#pragma unroll
        for (int o = 16; o; o >>= 1) {
            float vo = __shfl_xor_sync(0xffffffffu, v, o);
            int   jo = __shfl_xor_sync(0xffffffffu, j, o);
            if (vo > v || (vo == v && jo < j)) { v = vo; j = jo; }
        }
        if (lane == 0) {
            g_selidx[w * 8 + t] = j;
            float p = expf(v - m) / sum;
            g_selmask[w * 8 + t] = (p > 1e-10f) ? 1 : 0;
        }
        int owner = j & 31, rr = j >> 5;
        if (lane == owner) vals[rr] = -INFINITY;
    }
}

// ---------------- RoPE ----------------
__global__ void rope_table()
{
    int idx = blockIdx.x * blockDim.x + threadIdx.x;   // 2048*32
    if (idx >= S_LEN * 32) return;
    int p = idx & 31;
    int n = idx >> 5;
    double inv = pow(10000.0, -((double)(2 * p)) / 64.0);
    double a = (double)n * inv;
    g_rcs[idx * 2]     = (float)cos(a);
    g_rcs[idx * 2 + 1] = (float)sin(a);
}

__global__ void rope_apply()
{
    int idx = blockIdx.x * blockDim.x + threadIdx.x;   // 40 * 2048 * 32
    if (idx >= 40 * S_LEN * 32) return;
    int p = idx & 31;
    int n = (idx >> 5) & (S_LEN - 1);
    int hh = idx >> 16;                                // 0..39
    float c = g_rcs[(n * 32 + p) * 2];
    float s = g_rcs[(n * 32 + p) * 2 + 1];
    const float* src; float* dst;
    if (hh < 32) {
        src = g_qkv + (size_t)n * QKV_W + hh * DH_;
        dst = g_rq + ((size_t)hh * S_LEN + n) * DH_;
    } else {
        int h = hh - 32;
        src = g_qkv + (size_t)n * QKV_W + DIM_ + h * DH_;
        dst = g_rk + ((size_t)h * S_LEN + n) * DH_;
    }
    float x1 = src[2 * p], x2 = src[2 * p + 1];
    dst[2 * p]     = x1 * c - x2 * s;
    dst[2 * p + 1] = x1 * s + x2 * c;
}

// ---------------- fine (selected-block) attention ----------------
__global__ void fine_kernel()
{
    __shared__ float sp[8][144];
    int w = (blockIdx.x * blockDim.x + threadIdx.x) >> 5;
    int lane = threadIdx.x & 31, wl = (threadIdx.x >> 5) & 7;
    if (w >= HEADS_ * S_LEN) return;
    int hg = w >> 11, n = w & (S_LEN - 1);
    int h = hg >> 2;
    const float* q = g_rq + (size_t)w * 64;
    const int* sidx = g_selidx + (h * S_LEN + n) * 8;
    const unsigned char* smk = g_selmask + (h * S_LEN + n) * 8;
    int ownb = n >> 4;
    float m = -1e38f;
    for (int j = lane; j < 144; j += 32) {
        int bsel = j >> 4, off = j & 15;
        float s = NEGV;
        int blk; bool valid;
        if (bsel < 8) { blk = sidx[bsel]; valid = smk[bsel] != 0; }
        else          { blk = ownb;       valid = (n & 15) >= off; }
        if (valid) {
            int t = blk * 16 + off;
            const float* kr = g_rk + ((size_t)h * S_LEN + t) * 64;
            float acc = 0.f;
#pragma unroll
            for (int d = 0; d < 64; ++d) acc = fmaf(q[d], kr[d], acc);
            s = acc * SCALE_;
        }
        sp[wl][j] = s;
        m = fmaxf(m, s);
    }
#pragma unroll
    for (int o = 16; o; o >>= 1) m = fmaxf(m, __shfl_xor_sync(0xffffffffu, m, o));
    __syncwarp();
    float sum = 0.f;
    for (int j = lane; j < 144; j += 32) { float e = expf(sp[wl][j] - m); sp[wl][j] = e; sum += e; }
#pragma unroll
    for (int o = 16; o; o >>= 1) sum += __shfl_xor_sync(0xffffffffu, sum, o);
    __syncwarp();
    float inv = 1.f / sum;
    float a0 = 0.f, a1 = 0.f;
    for (int j = 0; j < 144; ++j) {
        int bsel = j >> 4, off = j & 15;
        int blk = (bsel < 8) ? sidx[bsel] : ownb;
        int t = blk * 16 + off;
        const float* vr = g_qkv + (size_t)t * QKV_W + DIM_ + 512 + h * DH_;
        float p = sp[wl][j];
        a0 = fmaf(p, vr[lane], a0);
        a1 = fmaf(p, vr[lane + 32], a1);
    }
    g_fout[(size_t)w * 64 + lane]      = a0 * inv;
    g_fout[(size_t)w * 64 + lane + 32] = a1 * inv;
}

// ---------------- sliding-window attention ----------------
__global__ void slide_kernel()
{
    __shared__ float sp[8][65];
    int w = (blockIdx.x * blockDim.x + threadIdx.x) >> 5;
    int lane = threadIdx.x & 31, wl = (threadIdx.x >> 5) & 7;
    if (w >= HEADS_ * S_LEN) return;
    int hg = w >> 11, n = w & (S_LEN - 1);
    int h = hg >> 2;
    const float* q = g_rq + (size_t)w * 64;
    int lo = n - 64; if (lo < 0) lo = 0;
    int cnt = n - lo + 1;                       // <= 65
    float m = -1e38f;
    for (int jj = lane; jj < cnt; jj += 32) {
        int t = lo + jj;
        const float* kr = g_rk + ((size_t)h * S_LEN + t) * 64;
        float acc = 0.f;
#pragma unroll
        for (int d = 0; d < 64; ++d) acc = fmaf(q[d], kr[d], acc);
        float s = acc * SCALE_;
        sp[wl][jj] = s;
        m = fmaxf(m, s);
    }
#pragma unroll
    for (int o = 16; o; o >>= 1) m = fmaxf(m, __shfl_xor_sync(0xffffffffu, m, o));
    __syncwarp();
    float sum = 0.f;
    for (int jj = lane; jj < cnt; jj += 32) { float e = expf(sp[wl][jj] - m); sp[wl][jj] = e; sum += e; }
#pragma unroll
    for (int o = 16; o; o >>= 1) sum += __shfl_xor_sync(0xffffffffu, sum, o);
    __syncwarp();
    float inv = 1.f / sum;
    float a0 = 0.f, a1 = 0.f;
    for (int jj = 0; jj < cnt; ++jj) {
        int t = lo + jj;
        const float* vr = g_qkv + (size_t)t * QKV_W + DIM_ + 512 + h * DH_;
        float p = sp[wl][jj];
        a0 = fmaf(p, vr[lane], a0);
        a1 = fmaf(p, vr[lane + 32], a1);
    }
    g_sout[(size_t)w * 64 + lane]      = a0 * inv;
    g_sout[(size_t)w * 64 + lane + 32] = a1 * inv;
}

// ---------------- gated combine ----------------
__global__ void combine_kernel()
{
    int idx = blockIdx.x * blockDim.x + threadIdx.x;   // 2048*2048
    if (idx >= S_LEN * DIM_) return;
    int col = idx & (DIM_ - 1);
    int n = idx >> 11;
    int hg = col >> 6;
    float gg0 = g_gate[n * 96 + hg * 3];
    float gg1 = g_gate[n * 96 + hg * 3 + 1];
    float gg2 = g_gate[n * 96 + hg * 3 + 2];
    size_t src = ((size_t)hg * S_LEN + n) * 64 + (col & 63);
    g_pre[idx] = gg0 * g_cout[src] + gg1 * g_fout[src] + gg2 * g_sout[src];
}

// ---------------- launcher ----------------
extern "C" void kernel_launch(void* const* d_in, const int* in_sizes, int n_in,
                              void* d_out, int out_size)
{
    const float* x      = (const float*)d_in[0];
    const float* w_qkv  = (const float*)d_in[1];
    const float* k_pos  = (const float*)d_in[2];
    const float* v_pos  = (const float*)d_in[3];
    const float* k_cw1  = (const float*)d_in[4];
    const float* k_cb1  = (const float*)d_in[5];
    const float* k_cw2  = (const float*)d_in[6];
    const float* k_cb2  = (const float*)d_in[7];
    const float* v_cw1  = (const float*)d_in[8];
    const float* v_cb1  = (const float*)d_in[9];
    const float* v_cw2  = (const float*)d_in[10];
    const float* v_cb2  = (const float*)d_in[11];
    const float* mem_ck = (const float*)d_in[12];
    const float* mem_cv = (const float*)d_in[13];
    const float* w_gate = (const float*)d_in[14];
    const float* b_gate = (const float*)d_in[15];
    const float* w_out  = (const float*)d_in[16];
    float* out = (float*)d_out;

    float *qkv, *kb, *vb, *h1, *body, *gate, *pre;
    cudaGetSymbolAddress((void**)&qkv,  g_qkv);
    cudaGetSymbolAddress((void**)&kb,   g_kb);
    cudaGetSymbolAddress((void**)&vb,   g_vb);
    cudaGetSymbolAddress((void**)&h1,   g_h1);
    cudaGetSymbolAddress((void**)&body, g_body);
    cudaGetSymbolAddress((void**)&gate, g_gate);
    cudaGetSymbolAddress((void**)&pre,  g_pre);

    // 1) qkv projection: (2048x2048) @ (2048x3072)
    sgemm_kernel<0><<<dim3(QKV_W / 128, S_LEN / 128), 256>>>(x, w_qkv, nullptr, qkv,
                                                             S_LEN, QKV_W, DIM_);
    // 2) compression inputs
    build_kb_vb<<<(KVH_ * NC_ * CDIM_) / 256, 256>>>(k_pos, v_pos);
    // 3) K compression MLP
    sgemm_kernel<1><<<dim3(8, 8), 256>>>(kb, k_cw1, k_cb1, h1, 1024, 1024, 1024);
    sgemm_kernel<0><<<dim3(1, 8), 256>>>(h1, k_cw2, k_cb2, body, 1024, 64, 1024);
    {
        float* ck; cudaGetSymbolAddress((void**)&ck, g_ck);
        assemble_c<<<(KVH_ * 129 * DH_ + 255) / 256, 256>>>(mem_ck, ck);
    }
    // 4) V compression MLP
    sgemm_kernel<1><<<dim3(8, 8), 256>>>(vb, v_cw1, v_cb1, h1, 1024, 1024, 1024);
    sgemm_kernel<0><<<dim3(1, 8), 256>>>(h1, v_cw2, v_cb2, body, 1024, 64, 1024);
    {
        float* cv; cudaGetSymbolAddress((void**)&cv, g_cv);
        assemble_c<<<(KVH_ * 129 * DH_ + 255) / 256, 256>>>(mem_cv, cv);
    }
    // 5) compression attention + importance/top-k
    csim_kernel<<<HEADS_ * S_LEN / 8, 256>>>();
    cout_kernel<<<HEADS_ * S_LEN / 8, 256>>>();
    topk_kernel<<<KVH_ * S_LEN / 8, 256>>>();
    // 6) RoPE
    rope_table<<<(S_LEN * 32) / 256, 256>>>();
    rope_apply<<<(40 * S_LEN * 32) / 256, 256>>>();
    // 7) fine + sliding attention
    fine_kernel<<<HEADS_ * S_LEN / 8, 256>>>();
    slide_kernel<<<HEADS_ * S_LEN / 8, 256>>>();
    // 8) gates
    sgemm_kernel<2><<<dim3(1, S_LEN / 128), 256>>>(x, w_gate, b_gate, gate,
                                                   S_LEN, 96, DIM_);
    // 9) combine + output projection
    combine_kernel<<<(S_LEN * DIM_) / 256, 256>>>();
    sgemm_kernel<0><<<dim3(DIM_ / 128, S_LEN / 128), 256>>>(pre, w_out, nullptr, out,
                                                            S_LEN, DIM_, DIM_);
}

// round 2
// speedup vs baseline: 2.6773x; 2.6773x over previous
#include <cuda_runtime.h>
#include <math.h>

// ---------------- problem constants ----------------
#define S_LEN 2048
#define QKV_W 3072
#define DIM_  2048
#define DH_   64
#define KVH_  8
#define HEADS_ 32
#define CDIM_ 1024
#define NC_   128
#define NEGV  (-1e30f)
#define SCALE_ 0.125f

// ---------------- scratch ----------------
__device__ float g_qkv [S_LEN * QKV_W];
__device__ float g_kb  [KVH_ * NC_ * CDIM_];
__device__ float g_vb  [KVH_ * NC_ * CDIM_];
__device__ float g_h1  [KVH_ * NC_ * CDIM_];
__device__ float g_body[KVH_ * NC_ * DH_];
__device__ float g_ck  [KVH_ * 129 * DH_];
__device__ float g_cv  [KVH_ * 129 * DH_];
__device__ float g_csim[HEADS_ * S_LEN * 129];
__device__ float g_cout[HEADS_ * S_LEN * DH_];
__device__ float g_fout[HEADS_ * S_LEN * DH_];
__device__ float g_sout[HEADS_ * S_LEN * DH_];
__device__ float g_rq  [HEADS_ * S_LEN * DH_];
__device__ float g_rk  [KVH_  * S_LEN * DH_];
__device__ float g_rcs [S_LEN * 32 * 2];
__device__ int           g_selidx [KVH_ * S_LEN * 8];
__device__ unsigned char g_selmask[KVH_ * S_LEN * 8];
__device__ float g_gate[S_LEN * 96];
__device__ float g_pre [S_LEN * DIM_];

// ================= fast 128x128x16 double-buffered SGEMM =================
// requires M%128==0, N%128==0, K%16==0. ACT: 0 none, 1 relu.
template <int ACT>
__global__ void __launch_bounds__(256, 2)
sgemm128(const float* __restrict__ A, const float* __restrict__ B,
         const float* __restrict__ bias, float* __restrict__ C,
         int M, int N, int K)
{
    __shared__ float As[2][16][128];
    __shared__ float Bs[2][16][128];
    const int tid = threadIdx.x;
    const int bx = blockIdx.x, by = blockIdx.y;
    const float* Ab = A + (size_t)by * 128 * K;
    const float* Bb = B + (size_t)bx * 128;

    const int arow = tid >> 2;           // 0..63
    const int ac4  = (tid & 3) << 2;     // 0,4,8,12
    const int bk   = tid >> 5;           // 0..7
    const int bc4  = (tid & 31) << 2;    // 0..124

    float4 ra0, ra1, rb0, rb1;
    // prologue: tile 0 -> buf 0
    ra0 = *(const float4*)(Ab + (size_t)arow * K + ac4);
    ra1 = *(const float4*)(Ab + (size_t)(arow + 64) * K + ac4);
    rb0 = *(const float4*)(Bb + (size_t)bk * N + bc4);
    rb1 = *(const float4*)(Bb + (size_t)(bk + 8) * N + bc4);
    As[0][ac4 + 0][arow] = ra0.x; As[0][ac4 + 1][arow] = ra0.y;
    As[0][ac4 + 2][arow] = ra0.z; As[0][ac4 + 3][arow] = ra0.w;
    As[0][ac4 + 0][arow + 64] = ra1.x; As[0][ac4 + 1][arow + 64] = ra1.y;
    As[0][ac4 + 2][arow + 64] = ra1.z; As[0][ac4 + 3][arow + 64] = ra1.w;
    *(float4*)&Bs[0][bk][bc4]     = rb0;
    *(float4*)&Bs[0][bk + 8][bc4] = rb1;
    __syncthreads();

    float acc[8][8];
#pragma unroll
    for (int i = 0; i < 8; ++i)
#pragma unroll
        for (int j = 0; j < 8; ++j) acc[i][j] = 0.f;

    const int ty = tid >> 4, tx = tid & 15;
    const int ktiles = K >> 4;
    for (int kt = 0; kt < ktiles; ++kt) {
        const int cur = kt & 1, nxt = cur ^ 1;
        const bool more = (kt + 1 < ktiles);
        if (more) {
            const float* Ak = Ab + (kt + 1) * 16;
            const float* Bk = Bb + (size_t)(kt + 1) * 16 * N;
            ra0 = *(const float4*)(Ak + (size_t)arow * K + ac4);
            ra1 = *(const float4*)(Ak + (size_t)(arow + 64) * K + ac4);
            rb0 = *(const float4*)(Bk + (size_t)bk * N + bc4);
            rb1 = *(const float4*)(Bk + (size_t)(bk + 8) * N + bc4);
        }
#pragma unroll
        for (int kk = 0; kk < 16; ++kk) {
            float a[8], b[8];
            *(float4*)&a[0] = *(const float4*)&As[cur][kk][ty * 8];
            *(float4*)&a[4] = *(const float4*)&As[cur][kk][ty * 8 + 4];
            *(float4*)&b[0] = *(const float4*)&Bs[cur][kk][tx * 8];
            *(float4*)&b[4] = *(const float4*)&Bs[cur][kk][tx * 8 + 4];
#pragma unroll
            for (int i = 0; i < 8; ++i)
#pragma unroll
                for (int j = 0; j < 8; ++j)
                    acc[i][j] = fmaf(a[i], b[j], acc[i][j]);
        }
        if (more) {
            As[nxt][ac4 + 0][arow] = ra0.x; As[nxt][ac4 + 1][arow] = ra0.y;
            As[nxt][ac4 + 2][arow] = ra0.z; As[nxt][ac4 + 3][arow] = ra0.w;
            As[nxt][ac4 + 0][arow + 64] = ra1.x; As[nxt][ac4 + 1][arow + 64] = ra1.y;
            As[nxt][ac4 + 2][arow + 64] = ra1.z; As[nxt][ac4 + 3][arow + 64] = ra1.w;
            *(float4*)&Bs[nxt][bk][bc4]     = rb0;
            *(float4*)&Bs[nxt][bk + 8][bc4] = rb1;
        }
        __syncthreads();
    }

    const int col0 = bx * 128 + tx * 8;
    float bb[8];
#pragma unroll
    for (int j = 0; j < 8; ++j) bb[j] = bias ? bias[col0 + j] : 0.f;
#pragma unroll
    for (int i = 0; i < 8; ++i) {
        const int row = by * 128 + ty * 8 + i;
        float* cr = C + (size_t)row * N + col0;
        float4 v0, v1;
        float t[8];
#pragma unroll
        for (int j = 0; j < 8; ++j) {
            float v = acc[i][j] + bb[j];
            if (ACT == 1) v = fmaxf(v, 0.f);
            t[j] = v;
        }
        v0.x = t[0]; v0.y = t[1]; v0.z = t[2]; v0.w = t[3];
        v1.x = t[4]; v1.y = t[5]; v1.z = t[6]; v1.w = t[7];
        *(float4*)cr = v0;
        *(float4*)(cr + 4) = v1;
    }
}

// ================= skinny GEMM (N small): one block per RPB rows ==========
// ACT: 0 none, 2 sigmoid. blockDim=256; active threads NCOL*NSL. K%128==0.
template <int ACT, int NCOL, int NSL, int RPB>
__global__ void skinny_gemm(const float* __restrict__ A, const float* __restrict__ B,
                            const float* __restrict__ bias, float* __restrict__ C,
                            int N, int K)
{
    __shared__ float sA[RPB][128];
    __shared__ float sred[NSL][RPB][NCOL];
    const int tid = threadIdx.x;
    const int row0 = blockIdx.x * RPB;
    const int c = tid % NCOL, sl = tid / NCOL;
    const bool active = sl < NSL;
    const int kper = 128 / NSL;
    float acc[RPB];
#pragma unroll
    for (int r = 0; r < RPB; ++r) acc[r] = 0.f;

    for (int k0 = 0; k0 < K; k0 += 128) {
        __syncthreads();
        for (int i = tid; i < RPB * 128; i += 256) {
            int r = i >> 7, kk = i & 127;
            sA[r][kk] = A[(size_t)(row0 + r) * K + k0 + kk];
        }
        __syncthreads();
        if (active) {
            for (int kk = sl * kper; kk < (sl + 1) * kper; ++kk) {
                float b = B[(size_t)(k0 + kk) * N + c];
#pragma unroll
                for (int r = 0; r < RPB; ++r) acc[r] = fmaf(sA[r][kk], b, acc[r]);
            }
        }
    }
    if (active) {
#pragma unroll
        for (int r = 0; r < RPB; ++r) sred[sl][r][c] = acc[r];
    }
    __syncthreads();
    for (int i = tid; i < RPB * NCOL; i += 256) {
        int r = i / NCOL, cc = i % NCOL;
        float s = 0.f;
#pragma unroll
        for (int q = 0; q < NSL; ++q) s += sred[q][r][cc];
        if (bias) s += bias[cc];
        if (ACT == 2) s = 1.f / (1.f + expf(-s));
        C[(size_t)(row0 + r) * N + cc] = s;
    }
}

// ---------------- kb/vb construction ----------------
__global__ void build_kb_vb(const float* __restrict__ k_pos, const float* __restrict__ v_pos)
{
    int idx = blockIdx.x * blockDim.x + threadIdx.x;
    if (idx >= KVH_ * NC_ * CDIM_) return;
    int d = idx & 63;
    int i = (idx >> 6) & 15;
    int c = (idx >> 10) & 127;
    int h = idx >> 17;
    int t = c * 16 + i;
    float kv = g_qkv[(size_t)t * QKV_W + DIM_ + h * DH_ + d];
    float vv = g_qkv[(size_t)t * QKV_W + DIM_ + 512 + h * DH_ + d];
    g_kb[idx] = kv + k_pos[(h * 16 + i) * 64 + d];
    g_vb[idx] = vv + v_pos[(h * 16 + i) * 64 + d];
}

// ---------------- assemble ck/cv ----------------
__global__ void assemble_c(const float* __restrict__ mem, float* __restrict__ dst)
{
    int idx = blockIdx.x * blockDim.x + threadIdx.x;
    if (idx >= KVH_ * 129 * DH_) return;
    int d = idx % 64;
    int j = (idx / 64) % 129;
    int h = idx / (64 * 129);
    dst[idx] = (j == 0) ? mem[h * 64 + d] : g_body[((h * NC_) + (j - 1)) * 64 + d];
}

// ---------------- compression attention: sim + softmax + V (fused) --------
__global__ void csoft_kernel()
{
    __shared__ float sp[8][129];
    int gw = (blockIdx.x * blockDim.x + threadIdx.x) >> 5;
    int lane = threadIdx.x & 31, wl = (threadIdx.x >> 5) & 7;
    if (gw >= HEADS_ * S_LEN) return;
    int hg = gw >> 11, n = gw & (S_LEN - 1);
    int h = hg >> 2;
    const float* q = g_qkv + (size_t)n * QKV_W + hg * DH_;
    float q0 = q[lane], q1 = q[lane + 32];
    const float* ckh = g_ck + h * 129 * 64;
    const int nvalid = (n >> 4) + 1;       // j valid iff j==0 or 16j<=n

    float m = -1e38f;
    for (int j = 0; j < nvalid; ++j) {
        const float* kr = ckh + j * 64;
        float s = q0 * kr[lane] + q1 * kr[lane + 32];
#pragma unroll
        for (int o = 16; o; o >>= 1) s += __shfl_xor_sync(0xffffffffu, s, o);
        s *= SCALE_;
        if (lane == 0) sp[wl][j] = s;
        m = fmaxf(m, s);
    }
    __syncwarp();
    // raw csim out (for topk)
    float* out = g_csim + (size_t)gw * 129;
    for (int j = lane; j < 129; j += 32) out[j] = (j < nvalid) ? sp[wl][j] : NEGV;
    // softmax
    float sum = 0.f;
    for (int j = lane; j < nvalid; j += 32) {
        float e = expf(sp[wl][j] - m);
        sp[wl][j] = e;
        sum += e;
    }
#pragma unroll
    for (int o = 16; o; o >>= 1) sum += __shfl_xor_sync(0xffffffffu, sum, o);
    __syncwarp();
    float inv = 1.f / sum;
    const float* cvh = g_cv + h * 129 * 64;
    float a0 = 0.f, a1 = 0.f;
    for (int j = 0; j < nvalid; ++j) {
        float p = sp[wl][j];
        a0 = fmaf(p, cvh[j * 64 + lane], a0);
        a1 = fmaf(p, cvh[j * 64 + lane + 32], a1);
    }
    g_cout[(size_t)gw * 64 + lane]      = a0 * inv;
    g_cout[(size_t)gw * 64 + lane + 32] = a1 * inv;
}

// ---------------- importance + top-8 selection ----------------
__global__ void topk_kernel()
{
    int w = (blockIdx.x * blockDim.x + threadIdx.x) >> 5;
    int lane = threadIdx.x & 31;
    if (w >= KVH_ * S_LEN) return;
    int h = w >> 11, n = w & (S_LEN - 1);
    float vals[4];
    int js[4];
#pragma unroll
    for (int r = 0; r < 4; ++r) {
        int jj = lane + r * 32;
        float s = 0.f;
        for (int g = 0; g < 4; ++g)
            s += g_csim[(((size_t)(h * 4 + g) * S_LEN + n) * 129) + jj + 1];
        vals[r] = s * 0.25f;
        js[r] = jj;
    }
    float m = -1000.f;
#pragma unroll
    for (int r = 0; r < 4; ++r) m = fmaxf(m, vals[r]);
#pragma unroll
    for (int o = 16; o; o >>= 1) m = fmaxf(m, __shfl_xor_sync(0xffffffffu, m, o));
    float sum = 0.f;
#pragma unroll
    for (int r = 0; r < 4; ++r) sum += expf(vals[r] - m);
#pragma unroll
    for (int o = 16; o; o >>= 1) sum += __shfl_xor_sync(0xffffffffu, sum, o);
    sum += expf(-1000.f - m);
    for (int t = 0; t < 8; ++t) {
        float bv = vals[0]; int bj = js[0];
#pragma unroll
        for (int r = 1; r < 4; ++r)
            if (vals[r] > bv || (vals[r] == bv && js[r] < bj)) { bv = vals[r]; bj = js[r]; }
        float v = bv; int j = bj;
#pragma unroll
        for (int o = 16; o; o >>= 1) {
            float vo = __shfl_xor_sync(0xffffffffu, v, o);
            int   jo = __shfl_xor_sync(0xffffffffu, j, o);
            if (vo > v || (vo == v && jo < j)) { v = vo; j = jo; }
        }
        if (lane == 0) {
            g_selidx[w * 8 + t] = j;
            float p = expf(v - m) / sum;
            g_selmask[w * 8 + t] = (p > 1e-10f) ? 1 : 0;
        }
        int owner = j & 31, rr = j >> 5;
        if (lane == owner) vals[rr] = -INFINITY;
    }
}

// ---------------- RoPE ----------------
__global__ void rope_table()
{
    int idx = blockIdx.x * blockDim.x + threadIdx.x;
    if (idx >= S_LEN * 32) return;
    int p = idx & 31;
    int n = idx >> 5;
    double inv = pow(10000.0, -((double)(2 * p)) / 64.0);
    double a = (double)n * inv;
    g_rcs[idx * 2]     = (float)cos(a);
    g_rcs[idx * 2 + 1] = (float)sin(a);
}

__global__ void rope_apply()
{
    int idx = blockIdx.x * blockDim.x + threadIdx.x;
    if (idx >= 40 * S_LEN * 32) return;
    int p = idx & 31;
    int n = (idx >> 5) & (S_LEN - 1);
    int hh = idx >> 16;
    float c = g_rcs[(n * 32 + p) * 2];
    float s = g_rcs[(n * 32 + p) * 2 + 1];
    const float* src; float* dst;
    if (hh < 32) {
        src = g_qkv + (size_t)n * QKV_W + hh * DH_;
        dst = g_rq + ((size_t)hh * S_LEN + n) * DH_;
    } else {
        int h = hh - 32;
        src = g_qkv + (size_t)n * QKV_W + DIM_ + h * DH_;
        dst = g_rk + ((size_t)h * S_LEN + n) * DH_;
    }
    float x1 = src[2 * p], x2 = src[2 * p + 1];
    dst[2 * p]     = x1 * c - x2 * s;
    dst[2 * p + 1] = x1 * s + x2 * c;
}

// ---------------- fine (selected-block) attention ----------------
__global__ void fine_kernel()
{
    __shared__ float sp[8][144];
    int gw = (blockIdx.x * blockDim.x + threadIdx.x) >> 5;
    int lane = threadIdx.x & 31, wl = (threadIdx.x >> 5) & 7;
    if (gw >= HEADS_ * S_LEN) return;
    int hg = gw >> 11, n = gw & (S_LEN - 1);
    int h = hg >> 2;
    const float* q = g_rq + (size_t)gw * 64;
    float q0 = q[lane], q1 = q[lane + 32];
    const int base = (h * S_LEN + n) * 8;
    const int ownb = n >> 4;

    float m = -1e38f;
    for (int j = 0; j < 144; ++j) {
        int bsel = j >> 4, off = j & 15;
        int blk; bool valid;
        if (bsel < 8) { blk = g_selidx[base + bsel]; valid = g_selmask[base + bsel] != 0; }
        else          { blk = ownb;                  valid = (n & 15) >= off; }
        float s = NEGV;
        if (valid) {
            const float* kr = g_rk + ((size_t)h * S_LEN + blk * 16 + off) * 64;
            float t = q0 * kr[lane] + q1 * kr[lane + 32];
#pragma unroll
            for (int o = 16; o; o >>= 1) t += __shfl_xor_sync(0xffffffffu, t, o);
            s = t * SCALE_;
        }
        if (lane == 0) sp[wl][j] = s;
        m = fmaxf(m, s);
    }
    __syncwarp();
    float sum = 0.f;
    for (int j = lane; j < 144; j += 32) {
        float e = expf(sp[wl][j] - m);
        sp[wl][j] = e;
        sum += e;
    }
#pragma unroll
    for (int o = 16; o; o >>= 1) sum += __shfl_xor_sync(0xffffffffu, sum, o);
    __syncwarp();
    float inv = 1.f / sum;
    float a0 = 0.f, a1 = 0.f;
    for (int j = 0; j < 144; ++j) {
        int bsel = j >> 4, off = j & 15;
        int blk = (bsel < 8) ? g_selidx[base + bsel] : ownb;
        int t = blk * 16 + off;
        const float* vr = g_qkv + (size_t)t * QKV_W + DIM_ + 512 + h * DH_;
        float p = sp[wl][j];
        a0 = fmaf(p, vr[lane], a0);
        a1 = fmaf(p, vr[lane + 32], a1);
    }
    g_fout[(size_t)gw * 64 + lane]      = a0 * inv;
    g_fout[(size_t)gw * 64 + lane + 32] = a1 * inv;
}

// ---------------- sliding-window attention ----------------
__global__ void slide_kernel()
{
    __shared__ float sp[8][65];
    int gw = (blockIdx.x * blockDim.x + threadIdx.x) >> 5;
    int lane = threadIdx.x & 31, wl = (threadIdx.x >> 5) & 7;
    if (gw >= HEADS_ * S_LEN) return;
    int hg = gw >> 11, n = gw & (S_LEN - 1);
    int h = hg >> 2;
    const float* q = g_rq + (size_t)gw * 64;
    float q0 = q[lane], q1 = q[lane + 32];
    int lo = n - 64; if (lo < 0) lo = 0;
    int cnt = n - lo + 1;

    float m = -1e38f;
    for (int jj = 0; jj < cnt; ++jj) {
        const float* kr = g_rk + ((size_t)h * S_LEN + lo + jj) * 64;
        float t = q0 * kr[lane] + q1 * kr[lane + 32];
#pragma unroll
        for (int o = 16; o; o >>= 1) t += __shfl_xor_sync(0xffffffffu, t, o);
        float s = t * SCALE_;
        if (lane == 0) sp[wl][jj] = s;
        m = fmaxf(m, s);
    }
    __syncwarp();
    float sum = 0.f;
    for (int jj = lane; jj < cnt; jj += 32) {
        float e = expf(sp[wl][jj] - m);
        sp[wl][jj] = e;
        sum += e;
    }
#pragma unroll
    for (int o = 16; o; o >>= 1) sum += __shfl_xor_sync(0xffffffffu, sum, o);
    __syncwarp();
    float inv = 1.f / sum;
    float a0 = 0.f, a1 = 0.f;
    for (int jj = 0; jj < cnt; ++jj) {
        const float* vr = g_qkv + (size_t)(lo + jj) * QKV_W + DIM_ + 512 + h * DH_;
        float p = sp[wl][jj];
        a0 = fmaf(p, vr[lane], a0);
        a1 = fmaf(p, vr[lane + 32], a1);
    }
    g_sout[(size_t)gw * 64 + lane]      = a0 * inv;
    g_sout[(size_t)gw * 64 + lane + 32] = a1 * inv;
}

// ---------------- gated combine ----------------
__global__ void combine_kernel()
{
    int idx = blockIdx.x * blockDim.x + threadIdx.x;
    if (idx >= S_LEN * DIM_) return;
    int col = idx & (DIM_ - 1);
    int n = idx >> 11;
    int hg = col >> 6;
    float gg0 = g_gate[n * 96 + hg * 3];
    float gg1 = g_gate[n * 96 + hg * 3 + 1];
    float gg2 = g_gate[n * 96 + hg * 3 + 2];
    size_t src = ((size_t)hg * S_LEN + n) * 64 + (col & 63);
    g_pre[idx] = gg0 * g_cout[src] + gg1 * g_fout[src] + gg2 * g_sout[src];
}

// ---------------- launcher ----------------
extern "C" void kernel_launch(void* const* d_in, const int* in_sizes, int n_in,
                              void* d_out, int out_size)
{
    const float* x      = (const float*)d_in[0];
    const float* w_qkv  = (const float*)d_in[1];
    const float* k_pos  = (const float*)d_in[2];
    const float* v_pos  = (const float*)d_in[3];
    const float* k_cw1  = (const float*)d_in[4];
    const float* k_cb1  = (const float*)d_in[5];
    const float* k_cw2  = (const float*)d_in[6];
    const float* k_cb2  = (const float*)d_in[7];
    const float* v_cw1  = (const float*)d_in[8];
    const float* v_cb1  = (const float*)d_in[9];
    const float* v_cw2  = (const float*)d_in[10];
    const float* v_cb2  = (const float*)d_in[11];
    const float* mem_ck = (const float*)d_in[12];
    const float* mem_cv = (const float*)d_in[13];
    const float* w_gate = (const float*)d_in[14];
    const float* b_gate = (const float*)d_in[15];
    const float* w_out  = (const float*)d_in[16];
    float* out = (float*)d_out;

    float *qkv, *kb, *vb, *h1, *body, *gate, *pre, *ck, *cv;
    cudaGetSymbolAddress((void**)&qkv,  g_qkv);
    cudaGetSymbolAddress((void**)&kb,   g_kb);
    cudaGetSymbolAddress((void**)&vb,   g_vb);
    cudaGetSymbolAddress((void**)&h1,   g_h1);
    cudaGetSymbolAddress((void**)&body, g_body);
    cudaGetSymbolAddress((void**)&gate, g_gate);
    cudaGetSymbolAddress((void**)&pre,  g_pre);
    cudaGetSymbolAddress((void**)&ck,   g_ck);
    cudaGetSymbolAddress((void**)&cv,   g_cv);

    // 1) qkv projection
    sgemm128<0><<<dim3(QKV_W / 128, S_LEN / 128), 256>>>(x, w_qkv, nullptr, qkv,
                                                         S_LEN, QKV_W, DIM_);
    // 2) compression inputs
    build_kb_vb<<<(KVH_ * NC_ * CDIM_) / 256, 256>>>(k_pos, v_pos);
    // 3) K compression MLP
    sgemm128<1><<<dim3(8, 8), 256>>>(kb, k_cw1, k_cb1, h1, 1024, 1024, 1024);
    skinny_gemm<0, 64, 4, 8><<<128, 256>>>(h1, k_cw2, k_cb2, body, 64, 1024);
    assemble_c<<<(KVH_ * 129 * DH_ + 255) / 256, 256>>>(mem_ck, ck);
    // 4) V compression MLP
    sgemm128<1><<<dim3(8, 8), 256>>>(vb, v_cw1, v_cb1, h1, 1024, 1024, 1024);
    skinny_gemm<0, 64, 4, 8><<<128, 256>>>(h1, v_cw2, v_cb2, body, 64, 1024);
    assemble_c<<<(KVH_ * 129 * DH_ + 255) / 256, 256>>>(mem_cv, cv);
    // 5) compression attention (fused) + top-k
    csoft_kernel<<<HEADS_ * S_LEN / 8, 256>>>();
    topk_kernel<<<KVH_ * S_LEN / 8, 256>>>();
    // 6) RoPE
    rope_table<<<(S_LEN * 32) / 256, 256>>>();
    rope_apply<<<(40 * S_LEN * 32) / 256, 256>>>();
    // 7) fine + sliding attention
    fine_kernel<<<HEADS_ * S_LEN / 8, 256>>>();
    slide_kernel<<<HEADS_ * S_LEN / 8, 256>>>();
    // 8) gates
    skinny_gemm<2, 96, 2, 8><<<256, 256>>>(x, w_gate, b_gate, gate, 96, DIM_);
    // 9) combine + output projection
    combine_kernel<<<(S_LEN * DIM_) / 256, 256>>>();
    sgemm128<0><<<dim3(DIM_ / 128, S_LEN / 128), 256>>>(pre, w_out, nullptr, out,
                                                        S_LEN, DIM_, DIM_);
}